// round 1
// baseline (speedup 1.0000x reference)
#include <cuda_runtime.h>

#define S_LEN   2048
#define DMODEL  2048
#define NH      16
#define HDIM    128
#define KV_DM   512      // KVH * HD
#define BQ      64
#define BK      64
#define DCH     32
#define NQT     (S_LEN / BQ)        // 32
#define HEAVY   204
#define RECENT  204
#define SEL     (S_LEN - RECENT)    // 1844
#define MASKW   (S_LEN + 1)         // 2049

__device__ float g_q[S_LEN * DMODEL];
__device__ float g_k[S_LEN * KV_DM];
__device__ float g_v[S_LEN * KV_DM];
__device__ float g_ctx[S_LEN * DMODEL];
__device__ float g_colpart[NH * NQT * S_LEN];   // per-(head, qtile) partial column sums

// ---------------------------------------------------------------------------
// Zero scratch
// ---------------------------------------------------------------------------
__global__ void zero_kernel(float* p, int n) {
    int i = blockIdx.x * 256 + threadIdx.x;
    if (i < n) p[i] = 0.0f;
}

// ---------------------------------------------------------------------------
// fp32 GEMM: C[M,N] = A[M,K] @ B[K,N] (+ bias[N]). 128x128 tile, BK=8,
// 256 threads, 8x8 per thread. M,N multiples of 128; K multiple of 8.
// ---------------------------------------------------------------------------
__global__ __launch_bounds__(256) void gemm_bias(
    const float* __restrict__ A, const float* __restrict__ B,
    const float* __restrict__ bias, float* __restrict__ C,
    int M, int N, int K)
{
    __shared__ float As[8][128];
    __shared__ float Bs[8][128];

    const int bm = blockIdx.y * 128;
    const int bn = blockIdx.x * 128;
    const int tid = threadIdx.x;

    const int arow = tid >> 1;          // 0..127
    const int akk  = (tid & 1) * 4;     // 0 or 4
    const int brow = tid >> 5;          // 0..7
    const int bcol = (tid & 31) * 4;    // 0..124

    const int ty = tid >> 4, tx = tid & 15;
    const int rr = ty * 8, cc = tx * 8;

    float acc[8][8];
#pragma unroll
    for (int i = 0; i < 8; i++)
#pragma unroll
        for (int j = 0; j < 8; j++) acc[i][j] = 0.0f;

    for (int k0 = 0; k0 < K; k0 += 8) {
        float4 av = *reinterpret_cast<const float4*>(&A[(size_t)(bm + arow) * K + k0 + akk]);
        float4 bv = *reinterpret_cast<const float4*>(&B[(size_t)(k0 + brow) * N + bn + bcol]);
        __syncthreads();
        As[akk + 0][arow] = av.x;
        As[akk + 1][arow] = av.y;
        As[akk + 2][arow] = av.z;
        As[akk + 3][arow] = av.w;
        *reinterpret_cast<float4*>(&Bs[brow][bcol]) = bv;
        __syncthreads();
#pragma unroll
        for (int kk = 0; kk < 8; kk++) {
            float a[8], b[8];
            *(float4*)&a[0] = *(const float4*)&As[kk][rr];
            *(float4*)&a[4] = *(const float4*)&As[kk][rr + 4];
            *(float4*)&b[0] = *(const float4*)&Bs[kk][cc];
            *(float4*)&b[4] = *(const float4*)&Bs[kk][cc + 4];
#pragma unroll
            for (int i = 0; i < 8; i++)
#pragma unroll
                for (int j = 0; j < 8; j++)
                    acc[i][j] = fmaf(a[i], b[j], acc[i][j]);
        }
    }

#pragma unroll
    for (int i = 0; i < 8; i++) {
        float* crow = &C[(size_t)(bm + rr + i) * N + bn];
#pragma unroll
        for (int jb = 0; jb < 8; jb += 4) {
            float4 v;
            v.x = acc[i][jb + 0];
            v.y = acc[i][jb + 1];
            v.z = acc[i][jb + 2];
            v.w = acc[i][jb + 3];
            if (bias) {
                const float4 bb = *(const float4*)&bias[bn + cc + jb];
                v.x += bb.x; v.y += bb.y; v.z += bb.z; v.w += bb.w;
            }
            *(float4*)&crow[cc + jb] = v;
        }
    }
}

// ---------------------------------------------------------------------------
// Two-pass flash attention per (head, 64-query tile).
// Pass 1: online (m, l).  Pass 2: recompute scores, p = exp(s-m)/l,
// accumulate O = P @ V and per-key column sums (deterministic partials).
// ---------------------------------------------------------------------------
__global__ __launch_bounds__(256) void attn_kernel() {
    const int qt = blockIdx.x;
    const int h  = blockIdx.y;
    const int kvh = h >> 2;     // GROUPS = 4
    const int tid = threadIdx.x;
    const int tx = tid & 15, ty = tid >> 4;
    const int r0 = ty * 4, c0 = tx * 4;
    const int qbase = qt * BQ;
    const float SCALE = 0.08838834764831845f;   // 128^-0.5

    __shared__ float s0[BK * BQ];     // sQt/sKt (score phase)  |  sPt (PV phase)
    __shared__ float s1[BK * 64];     // red (pass1)            |  sVh (pass2)
    __shared__ float m_sh[BQ], l_sh[BQ], inv_sh[BQ];

    float* const sQt = s0;                 // [DCH][BQ]
    float* const sKt = s0 + DCH * BQ;      // [DCH][BK]
    float* const sPt = s0;                 // [BK][BQ]
    float* const red = s1;                 // [BQ][16]
    float* const sVh = s1;                 // [BK][64]

    if (tid < BQ) { m_sh[tid] = -1e30f; l_sh[tid] = 0.0f; }

    const int lr = tid >> 2;            // 0..63 (row for tile loads)
    const int ld = (tid & 3) * 8;       // 0,8,16,24

    // ------------------------------- PASS 1 -------------------------------
    for (int kt = 0; kt <= qt; kt++) {
        float sc[4][4];
#pragma unroll
        for (int i = 0; i < 4; i++)
#pragma unroll
            for (int j = 0; j < 4; j++) sc[i][j] = 0.0f;

        for (int d0 = 0; d0 < HDIM; d0 += DCH) {
            __syncthreads();
            {
                const float* qp = &g_q[(size_t)(qbase + lr) * DMODEL + h * HDIM + d0 + ld];
                float4 a = *(const float4*)qp;
                float4 b = *(const float4*)(qp + 4);
                sQt[(ld + 0) * BQ + lr] = a.x;  sQt[(ld + 1) * BQ + lr] = a.y;
                sQt[(ld + 2) * BQ + lr] = a.z;  sQt[(ld + 3) * BQ + lr] = a.w;
                sQt[(ld + 4) * BQ + lr] = b.x;  sQt[(ld + 5) * BQ + lr] = b.y;
                sQt[(ld + 6) * BQ + lr] = b.z;  sQt[(ld + 7) * BQ + lr] = b.w;
                const float* kp = &g_k[(size_t)(kt * BK + lr) * KV_DM + kvh * HDIM + d0 + ld];
                float4 c = *(const float4*)kp;
                float4 d = *(const float4*)(kp + 4);
                sKt[(ld + 0) * BK + lr] = c.x;  sKt[(ld + 1) * BK + lr] = c.y;
                sKt[(ld + 2) * BK + lr] = c.z;  sKt[(ld + 3) * BK + lr] = c.w;
                sKt[(ld + 4) * BK + lr] = d.x;  sKt[(ld + 5) * BK + lr] = d.y;
                sKt[(ld + 6) * BK + lr] = d.z;  sKt[(ld + 7) * BK + lr] = d.w;
            }
            __syncthreads();
#pragma unroll 8
            for (int dk = 0; dk < DCH; dk++) {
                float4 av = *(const float4*)&sQt[dk * BQ + r0];
                float4 bv = *(const float4*)&sKt[dk * BK + c0];
                float a[4] = {av.x, av.y, av.z, av.w};
                float b[4] = {bv.x, bv.y, bv.z, bv.w};
#pragma unroll
                for (int i = 0; i < 4; i++)
#pragma unroll
                    for (int j = 0; j < 4; j++)
                        sc[i][j] = fmaf(a[i], b[j], sc[i][j]);
            }
        }
        // scale + causal mask
#pragma unroll
        for (int i = 0; i < 4; i++)
#pragma unroll
            for (int j = 0; j < 4; j++) {
                sc[i][j] *= SCALE;
                if (kt == qt && (c0 + j) > (r0 + i)) sc[i][j] = -1e30f;
            }
        // row max
#pragma unroll
        for (int i = 0; i < 4; i++) {
            float rm = fmaxf(fmaxf(sc[i][0], sc[i][1]), fmaxf(sc[i][2], sc[i][3]));
            red[(r0 + i) * 16 + tx] = rm;
        }
        __syncthreads();
        if (tid < BQ) {
            float tm = red[tid * 16];
#pragma unroll
            for (int j = 1; j < 16; j++) tm = fmaxf(tm, red[tid * 16 + j]);
            float mo = m_sh[tid];
            float mn = fmaxf(mo, tm);
            l_sh[tid] *= __expf(mo - mn);
            m_sh[tid] = mn;
        }
        __syncthreads();
        // sum of exp
#pragma unroll
        for (int i = 0; i < 4; i++) {
            float mrow = m_sh[r0 + i];
            float rs = 0.0f;
#pragma unroll
            for (int j = 0; j < 4; j++) rs += __expf(sc[i][j] - mrow);
            red[(r0 + i) * 16 + tx] = rs;
        }
        __syncthreads();
        if (tid < BQ) {
            float t = 0.0f;
#pragma unroll
            for (int j = 0; j < 16; j++) t += red[tid * 16 + j];
            l_sh[tid] += t;
        }
    }
    __syncthreads();
    if (tid < BQ) inv_sh[tid] = 1.0f / l_sh[tid];
    __syncthreads();

    // ------------------------------- PASS 2 -------------------------------
    float o[2][4][4];
#pragma unroll
    for (int hlf = 0; hlf < 2; hlf++)
#pragma unroll
        for (int i = 0; i < 4; i++)
#pragma unroll
            for (int j = 0; j < 4; j++) o[hlf][i][j] = 0.0f;

    for (int kt = 0; kt <= qt; kt++) {
        float sc[4][4];
#pragma unroll
        for (int i = 0; i < 4; i++)
#pragma unroll
            for (int j = 0; j < 4; j++) sc[i][j] = 0.0f;

        for (int d0 = 0; d0 < HDIM; d0 += DCH) {
            __syncthreads();
            {
                const float* qp = &g_q[(size_t)(qbase + lr) * DMODEL + h * HDIM + d0 + ld];
                float4 a = *(const float4*)qp;
                float4 b = *(const float4*)(qp + 4);
                sQt[(ld + 0) * BQ + lr] = a.x;  sQt[(ld + 1) * BQ + lr] = a.y;
                sQt[(ld + 2) * BQ + lr] = a.z;  sQt[(ld + 3) * BQ + lr] = a.w;
                sQt[(ld + 4) * BQ + lr] = b.x;  sQt[(ld + 5) * BQ + lr] = b.y;
                sQt[(ld + 6) * BQ + lr] = b.z;  sQt[(ld + 7) * BQ + lr] = b.w;
                const float* kp = &g_k[(size_t)(kt * BK + lr) * KV_DM + kvh * HDIM + d0 + ld];
                float4 c = *(const float4*)kp;
                float4 d = *(const float4*)(kp + 4);
                sKt[(ld + 0) * BK + lr] = c.x;  sKt[(ld + 1) * BK + lr] = c.y;
                sKt[(ld + 2) * BK + lr] = c.z;  sKt[(ld + 3) * BK + lr] = c.w;
                sKt[(ld + 4) * BK + lr] = d.x;  sKt[(ld + 5) * BK + lr] = d.y;
                sKt[(ld + 6) * BK + lr] = d.z;  sKt[(ld + 7) * BK + lr] = d.w;
            }
            __syncthreads();
#pragma unroll 8
            for (int dk = 0; dk < DCH; dk++) {
                float4 av = *(const float4*)&sQt[dk * BQ + r0];
                float4 bv = *(const float4*)&sKt[dk * BK + c0];
                float a[4] = {av.x, av.y, av.z, av.w};
                float b[4] = {bv.x, bv.y, bv.z, bv.w};
#pragma unroll
                for (int i = 0; i < 4; i++)
#pragma unroll
                    for (int j = 0; j < 4; j++)
                        sc[i][j] = fmaf(a[i], b[j], sc[i][j]);
            }
        }
        __syncthreads();   // all score reads of s0 done before overwriting as sPt

        // normalized probabilities -> sPt (transposed [key][query])
#pragma unroll
        for (int i = 0; i < 4; i++) {
            float mrow = m_sh[r0 + i];
            float il = inv_sh[r0 + i];
#pragma unroll
            for (int j = 0; j < 4; j++) {
                float s = sc[i][j] * SCALE;
                if (kt == qt && (c0 + j) > (r0 + i)) s = -1e30f;
                float p = __expf(s - mrow) * il;
                sPt[(c0 + j) * BQ + (r0 + i)] = p;
            }
        }
        __syncthreads();

        // deterministic column-sum partial (rotation avoids bank conflicts)
        if (tid < BK) {
            float cs = 0.0f;
            for (int r = 0; r < BQ; r++) cs += sPt[tid * BQ + ((r + tid) & (BQ - 1))];
            g_colpart[(size_t)(h * NQT + qt) * S_LEN + kt * BK + tid] = cs;
        }

        // O += P @ V, 64-wide halves of HD
#pragma unroll
        for (int hlf = 0; hlf < 2; hlf++) {
            __syncthreads();
            {
                const int vr = tid >> 2;          // 0..63
                const int vd = (tid & 3) * 16;    // 0,16,32,48
                const float* vp = &g_v[(size_t)(kt * BK + vr) * KV_DM + kvh * HDIM + hlf * 64 + vd];
                float4 x0 = *(const float4*)(vp + 0);
                float4 x1 = *(const float4*)(vp + 4);
                float4 x2 = *(const float4*)(vp + 8);
                float4 x3 = *(const float4*)(vp + 12);
                *(float4*)&sVh[vr * 64 + vd + 0]  = x0;
                *(float4*)&sVh[vr * 64 + vd + 4]  = x1;
                *(float4*)&sVh[vr * 64 + vd + 8]  = x2;
                *(float4*)&sVh[vr * 64 + vd + 12] = x3;
            }
            __syncthreads();
#pragma unroll 8
            for (int c = 0; c < BK; c++) {
                float4 av = *(const float4*)&sPt[c * BQ + r0];
                float4 bv = *(const float4*)&sVh[c * 64 + c0];
                float a[4] = {av.x, av.y, av.z, av.w};
                float b[4] = {bv.x, bv.y, bv.z, bv.w};
#pragma unroll
                for (int i = 0; i < 4; i++)
#pragma unroll
                    for (int j = 0; j < 4; j++)
                        o[hlf][i][j] = fmaf(a[i], b[j], o[hlf][i][j]);
            }
        }
    }

    // write context (already normalized): ctx[s][h*128 + d]
#pragma unroll
    for (int hlf = 0; hlf < 2; hlf++)
#pragma unroll
        for (int i = 0; i < 4; i++) {
            float4 v;
            v.x = o[hlf][i][0]; v.y = o[hlf][i][1];
            v.z = o[hlf][i][2]; v.w = o[hlf][i][3];
            *(float4*)&g_ctx[(size_t)(qbase + r0 + i) * DMODEL + h * HDIM + hlf * 64 + c0] = v;
        }
}

// ---------------------------------------------------------------------------
// Heavy-hitter mask: sum partials -> cur_scores, then 204x deterministic
// argmax (lowest index on ties, matching jax.lax.top_k).
// ---------------------------------------------------------------------------
__global__ __launch_bounds__(256) void topk_kernel(float* __restrict__ mask_out) {
    const int h = blockIdx.x;
    const int tid = threadIdx.x;
    __shared__ float vals[SEL];
    __shared__ float bv[256];
    __shared__ int   bi[256];

    for (int i = tid; i < SEL; i += 256) {
        float s = 0.0f;
        for (int qt = 0; qt < NQT; qt++)
            s += g_colpart[(size_t)(h * NQT + qt) * S_LEN + i];
        vals[i] = s;
    }
    float* mrow = mask_out + (size_t)h * MASKW;
    for (int i = tid; i < MASKW; i += 256)
        mrow[i] = (i >= (MASKW - RECENT)) ? 1.0f : 0.0f;
    __syncthreads();

    for (int it = 0; it < HEAVY; it++) {
        float best = -1.0f;
        int besti = SEL;
        for (int i = tid; i < SEL; i += 256) {
            float v = vals[i];
            if (v > best) { best = v; besti = i; }   // ascending scan keeps lowest idx on tie
        }
        bv[tid] = best; bi[tid] = besti;
        __syncthreads();
        for (int s = 128; s > 0; s >>= 1) {
            if (tid < s) {
                float ov = bv[tid + s]; int oi = bi[tid + s];
                if (ov > bv[tid] || (ov == bv[tid] && oi < bi[tid])) { bv[tid] = ov; bi[tid] = oi; }
            }
            __syncthreads();
        }
        if (tid == 0) { mrow[bi[0]] = 1.0f; vals[bi[0]] = -1.0f; }
        __syncthreads();
    }
}

// ---------------------------------------------------------------------------
extern "C" void kernel_launch(void* const* d_in, const int* in_sizes, int n_in,
                              void* d_out, int out_size) {
    (void)in_sizes; (void)n_in; (void)out_size;
    const float* hidden = (const float*)d_in[0];
    const float* q_w = (const float*)d_in[1];
    const float* q_b = (const float*)d_in[2];
    const float* k_w = (const float*)d_in[3];
    const float* k_b = (const float*)d_in[4];
    const float* v_w = (const float*)d_in[5];
    const float* v_b = (const float*)d_in[6];
    const float* o_w = (const float*)d_in[7];
    float* out = (float*)d_out;

    float *gq, *gk, *gv, *gctx, *gcp;
    cudaGetSymbolAddress((void**)&gq,   g_q);
    cudaGetSymbolAddress((void**)&gk,   g_k);
    cudaGetSymbolAddress((void**)&gv,   g_v);
    cudaGetSymbolAddress((void**)&gctx, g_ctx);
    cudaGetSymbolAddress((void**)&gcp,  g_colpart);

    const int ncp = NH * NQT * S_LEN;
    zero_kernel<<<(ncp + 255) / 256, 256>>>(gcp, ncp);

    dim3 blk(256);
    gemm_bias<<<dim3(DMODEL / 128, S_LEN / 128), blk>>>(hidden, q_w, q_b, gq, S_LEN, DMODEL, DMODEL);
    gemm_bias<<<dim3(KV_DM  / 128, S_LEN / 128), blk>>>(hidden, k_w, k_b, gk, S_LEN, KV_DM,  DMODEL);
    gemm_bias<<<dim3(KV_DM  / 128, S_LEN / 128), blk>>>(hidden, v_w, v_b, gv, S_LEN, KV_DM,  DMODEL);

    attn_kernel<<<dim3(NQT, NH), blk>>>();

    topk_kernel<<<NH, 256>>>(out + (size_t)S_LEN * DMODEL);

    gemm_bias<<<dim3(DMODEL / 128, S_LEN / 128), blk>>>(gctx, o_w, nullptr, out, S_LEN, DMODEL, DMODEL);
}

// round 2
// speedup vs baseline: 3.6206x; 3.6206x over previous
#include <cuda_runtime.h>
#include <cstdint>

#define S_LEN   2048
#define DMODEL  2048
#define NH      16
#define HDIM    128
#define KV_DM   512
#define BQ      64
#define NQT     (S_LEN / BQ)        // 32
#define HEAVY   204
#define RECENT  204
#define SEL     (S_LEN - RECENT)    // 1844
#define MASKW   (S_LEN + 1)         // 2049

__device__ float g_q[S_LEN * DMODEL];
__device__ float g_k[S_LEN * KV_DM];
__device__ float g_v[S_LEN * KV_DM];
__device__ float g_ctx[S_LEN * DMODEL];
__device__ float g_colpart[NH * NQT * S_LEN];
__device__ float g_scores[(size_t)NH * S_LEN * S_LEN];   // 256 MB scratch

// ---------------------------------------------------------------------------
__device__ __forceinline__ float tf32r(float x) {
    uint32_t u;
    asm("cvt.rna.tf32.f32 %0, %1;" : "=r"(u) : "f"(x));
    return __uint_as_float(u);
}
__device__ __forceinline__ float ex2f(float x) {
    float y;
    asm("ex2.approx.ftz.f32 %0, %1;" : "=f"(y) : "f"(x));
    return y;
}
__device__ __forceinline__ void mma_tf32(float* c, const uint32_t* a, const uint32_t* b) {
    asm volatile(
        "mma.sync.aligned.m16n8k8.row.col.f32.tf32.tf32.f32 "
        "{%0,%1,%2,%3}, {%4,%5,%6,%7}, {%8,%9}, {%0,%1,%2,%3};"
        : "+f"(c[0]), "+f"(c[1]), "+f"(c[2]), "+f"(c[3])
        : "r"(a[0]), "r"(a[1]), "r"(a[2]), "r"(a[3]), "r"(b[0]), "r"(b[1]));
}

__global__ void zero_kernel(float* p, int n) {
    int i = blockIdx.x * 256 + threadIdx.x;
    if (i < n) p[i] = 0.0f;
}

// ---------------------------------------------------------------------------
// tf32 GEMM: C[M,N] = A[M,K] @ B[K,N] (+ bias). BM=128, BK=32.
// ---------------------------------------------------------------------------
template<int BN, int WM, int WN>
__global__ __launch_bounds__(256) void gemm_tf32(
    const float* __restrict__ A, const float* __restrict__ Bm,
    const float* __restrict__ bias, float* __restrict__ C,
    int M, int N, int K)
{
    constexpr int BM = 128, BK = 32;
    constexpr int ASS = BK + 4;        // 36  (≡4 mod 32 -> conflict-free frags)
    constexpr int BSS = BN + 8;        // 136/72 (≡8 mod 32)
    constexpr int MI = WM / 16, NJ = WN / 8;
    constexpr int WARPS_M = BM / WM;
    constexpr int NB4 = BN / 32;
    constexpr int BT  = BN / 4;
    constexpr int KSB = 256 / BT;

    __shared__ float As[BM * ASS];
    __shared__ float Bs[BK * BSS];

    const int tid = threadIdx.x;
    const int lane = tid & 31, w = tid >> 5;
    const int wm0 = (w % WARPS_M) * WM;
    const int wn0 = (w / WARPS_M) * WN;
    const int bm = blockIdx.y * BM;
    const int bn = blockIdx.x * BN;

    const int ar = tid >> 3;           // 0..31
    const int ac = (tid & 7) * 4;      // 0..28
    const int bk = tid / BT;
    const int bcn = (tid % BT) * 4;

    float acc[MI][NJ][4];
#pragma unroll
    for (int mi = 0; mi < MI; mi++)
#pragma unroll
        for (int nj = 0; nj < NJ; nj++)
#pragma unroll
            for (int c = 0; c < 4; c++) acc[mi][nj][c] = 0.0f;

    float4 pa[4], pb[NB4];
#pragma unroll
    for (int i = 0; i < 4; i++)
        pa[i] = *(const float4*)&A[(size_t)(bm + ar + 32 * i) * K + ac];
#pragma unroll
    for (int i = 0; i < NB4; i++)
        pb[i] = *(const float4*)&Bm[(size_t)(bk + KSB * i) * N + bn + bcn];

    for (int k0 = 0; k0 < K; k0 += BK) {
        __syncthreads();
#pragma unroll
        for (int i = 0; i < 4; i++) {
            float4 v = pa[i];
            float4 t = make_float4(tf32r(v.x), tf32r(v.y), tf32r(v.z), tf32r(v.w));
            *(float4*)&As[(ar + 32 * i) * ASS + ac] = t;
        }
#pragma unroll
        for (int i = 0; i < NB4; i++) {
            float4 v = pb[i];
            float4 t = make_float4(tf32r(v.x), tf32r(v.y), tf32r(v.z), tf32r(v.w));
            *(float4*)&Bs[(bk + KSB * i) * BSS + bcn] = t;
        }
        __syncthreads();
        if (k0 + BK < K) {
#pragma unroll
            for (int i = 0; i < 4; i++)
                pa[i] = *(const float4*)&A[(size_t)(bm + ar + 32 * i) * K + k0 + BK + ac];
#pragma unroll
            for (int i = 0; i < NB4; i++)
                pb[i] = *(const float4*)&Bm[(size_t)(k0 + BK + bk + KSB * i) * N + bn + bcn];
        }
#pragma unroll
        for (int ks = 0; ks < 4; ks++) {
            const int kk = ks * 8;
            uint32_t af[MI][4], bf[NJ][2];
#pragma unroll
            for (int mi = 0; mi < MI; mi++) {
                int m0 = wm0 + 16 * mi + (lane >> 2);
                af[mi][0] = __float_as_uint(As[m0 * ASS + kk + (lane & 3)]);
                af[mi][1] = __float_as_uint(As[(m0 + 8) * ASS + kk + (lane & 3)]);
                af[mi][2] = __float_as_uint(As[m0 * ASS + kk + 4 + (lane & 3)]);
                af[mi][3] = __float_as_uint(As[(m0 + 8) * ASS + kk + 4 + (lane & 3)]);
            }
#pragma unroll
            for (int nj = 0; nj < NJ; nj++) {
                int n0 = wn0 + 8 * nj + (lane >> 2);
                bf[nj][0] = __float_as_uint(Bs[(kk + (lane & 3)) * BSS + n0]);
                bf[nj][1] = __float_as_uint(Bs[(kk + 4 + (lane & 3)) * BSS + n0]);
            }
#pragma unroll
            for (int mi = 0; mi < MI; mi++)
#pragma unroll
                for (int nj = 0; nj < NJ; nj++)
                    mma_tf32(acc[mi][nj], af[mi], bf[nj]);
        }
    }

#pragma unroll
    for (int mi = 0; mi < MI; mi++) {
#pragma unroll
        for (int nj = 0; nj < NJ; nj++) {
            int row = bm + wm0 + 16 * mi + (lane >> 2);
            int col = bn + wn0 + 8 * nj + 2 * (lane & 3);
            float bx = 0.0f, by = 0.0f;
            if (bias) { bx = bias[col]; by = bias[col + 1]; }
            float2 v0 = make_float2(acc[mi][nj][0] + bx, acc[mi][nj][1] + by);
            float2 v1 = make_float2(acc[mi][nj][2] + bx, acc[mi][nj][3] + by);
            *(float2*)&C[(size_t)row * N + col] = v0;
            *(float2*)&C[(size_t)(row + 8) * N + col] = v1;
        }
    }
}

// ---------------------------------------------------------------------------
// Causal scores GEMM: g_scores[h][q][k] = (Q_h K_h^T) * SCALE * LOG2E, masked.
// Block 128q x 128k, HD=128 inner. Skips fully-masked blocks.
// ---------------------------------------------------------------------------
__global__ __launch_bounds__(256) void scores_tf32() {
    constexpr int ASS = 36;
    const int nb = blockIdx.x, mb = blockIdx.y, h = blockIdx.z;
    if (nb > mb) return;
    const int kvh = h >> 2;

    __shared__ float Qs[128 * ASS];
    __shared__ float Ks[128 * ASS];

    const int tid = threadIdx.x;
    const int lane = tid & 31, w = tid >> 5;
    const int wm0 = (w & 1) * 64;
    const int wn0 = (w >> 1) * 32;
    const int ar = tid >> 3;
    const int ac = (tid & 7) * 4;

    float acc[4][4][4];
#pragma unroll
    for (int mi = 0; mi < 4; mi++)
#pragma unroll
        for (int nj = 0; nj < 4; nj++)
#pragma unroll
            for (int c = 0; c < 4; c++) acc[mi][nj][c] = 0.0f;

    const float* Qg = g_q + (size_t)(mb * 128) * DMODEL + h * HDIM;
    const float* Kg = g_k + (size_t)(nb * 128) * KV_DM + kvh * HDIM;

    float4 pq[4], pk[4];
#pragma unroll
    for (int i = 0; i < 4; i++) {
        pq[i] = *(const float4*)&Qg[(size_t)(ar + 32 * i) * DMODEL + ac];
        pk[i] = *(const float4*)&Kg[(size_t)(ar + 32 * i) * KV_DM + ac];
    }

    for (int k0 = 0; k0 < HDIM; k0 += 32) {
        __syncthreads();
#pragma unroll
        for (int i = 0; i < 4; i++) {
            float4 v = pq[i];
            *(float4*)&Qs[(ar + 32 * i) * ASS + ac] =
                make_float4(tf32r(v.x), tf32r(v.y), tf32r(v.z), tf32r(v.w));
            float4 u = pk[i];
            *(float4*)&Ks[(ar + 32 * i) * ASS + ac] =
                make_float4(tf32r(u.x), tf32r(u.y), tf32r(u.z), tf32r(u.w));
        }
        __syncthreads();
        if (k0 + 32 < HDIM) {
#pragma unroll
            for (int i = 0; i < 4; i++) {
                pq[i] = *(const float4*)&Qg[(size_t)(ar + 32 * i) * DMODEL + k0 + 32 + ac];
                pk[i] = *(const float4*)&Kg[(size_t)(ar + 32 * i) * KV_DM + k0 + 32 + ac];
            }
        }
#pragma unroll
        for (int ks = 0; ks < 4; ks++) {
            const int kk = ks * 8;
            uint32_t af[4][4], bf[4][2];
#pragma unroll
            for (int mi = 0; mi < 4; mi++) {
                int m0 = wm0 + 16 * mi + (lane >> 2);
                af[mi][0] = __float_as_uint(Qs[m0 * ASS + kk + (lane & 3)]);
                af[mi][1] = __float_as_uint(Qs[(m0 + 8) * ASS + kk + (lane & 3)]);
                af[mi][2] = __float_as_uint(Qs[m0 * ASS + kk + 4 + (lane & 3)]);
                af[mi][3] = __float_as_uint(Qs[(m0 + 8) * ASS + kk + 4 + (lane & 3)]);
            }
#pragma unroll
            for (int nj = 0; nj < 4; nj++) {
                int n0 = wn0 + 8 * nj + (lane >> 2);
                bf[nj][0] = __float_as_uint(Ks[n0 * ASS + kk + (lane & 3)]);
                bf[nj][1] = __float_as_uint(Ks[n0 * ASS + kk + 4 + (lane & 3)]);
            }
#pragma unroll
            for (int mi = 0; mi < 4; mi++)
#pragma unroll
                for (int nj = 0; nj < 4; nj++)
                    mma_tf32(acc[mi][nj], af[mi], bf[nj]);
        }
    }

    const float SCL2 = 0.08838834764831845f * 1.4426950408889634f;
    float* sh = g_scores + (size_t)h * S_LEN * S_LEN;
#pragma unroll
    for (int mi = 0; mi < 4; mi++) {
#pragma unroll
        for (int nj = 0; nj < 4; nj++) {
            int row = mb * 128 + wm0 + 16 * mi + (lane >> 2);
            int col = nb * 128 + wn0 + 8 * nj + 2 * (lane & 3);
            float2 v0, v1;
            v0.x = (col     <= row)     ? acc[mi][nj][0] * SCL2 : -1e30f;
            v0.y = (col + 1 <= row)     ? acc[mi][nj][1] * SCL2 : -1e30f;
            v1.x = (col     <= row + 8) ? acc[mi][nj][2] * SCL2 : -1e30f;
            v1.y = (col + 1 <= row + 8) ? acc[mi][nj][3] * SCL2 : -1e30f;
            *(float2*)&sh[(size_t)row * S_LEN + col] = v0;
            *(float2*)&sh[(size_t)(row + 8) * S_LEN + col] = v1;
        }
    }
}

// ---------------------------------------------------------------------------
// Attention over cached scores: pass0 rowmax, pass1 exp+l (in-place e),
// pass2 p = e/l -> colsums + P@V (tf32 mma).
// ---------------------------------------------------------------------------
__global__ __launch_bounds__(256) void attn_kernel() {
    const int qt = blockIdx.x, h = blockIdx.y;
    const int kvh = h >> 2;
    const int tid = threadIdx.x;
    const int lane = tid & 31, w = tid >> 5;
    const int tx = tid & 15, ty = tid >> 4;
    const int r0 = ty * 4, c0 = tx * 4;
    const int qbase = qt * BQ;

    __shared__ float sP[BQ * 68];
    __shared__ float Vs[64 * 72];
    __shared__ float red[BQ * 16];
    __shared__ float m_sh[BQ], inv_sh[BQ];

    float* sh = g_scores + (size_t)h * S_LEN * S_LEN;

    // ---------------- pass 0: row max ----------------
    float rm[4] = {-1e30f, -1e30f, -1e30f, -1e30f};
    for (int kt = 0; kt <= qt; kt++) {
#pragma unroll
        for (int i = 0; i < 4; i++) {
            float4 v = *(const float4*)&sh[(size_t)(qbase + r0 + i) * S_LEN + kt * 64 + c0];
            rm[i] = fmaxf(rm[i], fmaxf(fmaxf(v.x, v.y), fmaxf(v.z, v.w)));
        }
    }
#pragma unroll
    for (int i = 0; i < 4; i++) red[(r0 + i) * 16 + tx] = rm[i];
    __syncthreads();
    if (tid < BQ) {
        float m = red[tid * 16];
#pragma unroll
        for (int j = 1; j < 16; j++) m = fmaxf(m, red[tid * 16 + j]);
        m_sh[tid] = m;
    }
    __syncthreads();

    // ---------------- pass 1: e = 2^(s-m), l ----------------
    float mr[4];
#pragma unroll
    for (int i = 0; i < 4; i++) mr[i] = m_sh[r0 + i];
    float ls[4] = {0.f, 0.f, 0.f, 0.f};
    for (int kt = 0; kt <= qt; kt++) {
#pragma unroll
        for (int i = 0; i < 4; i++) {
            size_t idx = (size_t)(qbase + r0 + i) * S_LEN + kt * 64 + c0;
            float4 v = *(const float4*)&sh[idx];
            v.x = ex2f(v.x - mr[i]);
            v.y = ex2f(v.y - mr[i]);
            v.z = ex2f(v.z - mr[i]);
            v.w = ex2f(v.w - mr[i]);
            *(float4*)&sh[idx] = v;
            ls[i] += (v.x + v.y) + (v.z + v.w);
        }
    }
    __syncthreads();
#pragma unroll
    for (int i = 0; i < 4; i++) red[(r0 + i) * 16 + tx] = ls[i];
    __syncthreads();
    if (tid < BQ) {
        float l = 0.0f;
#pragma unroll
        for (int j = 0; j < 16; j++) l += red[tid * 16 + j];
        inv_sh[tid] = 1.0f / l;
    }
    __syncthreads();

    // ---------------- pass 2: p, colsums, P@V ----------------
    const int wm0 = (w & 1) * 32;
    const int wn0 = (w >> 1) * 16;
    float o[2][2][2][4];
#pragma unroll
    for (int a = 0; a < 2; a++)
#pragma unroll
        for (int b = 0; b < 2; b++)
#pragma unroll
            for (int c = 0; c < 2; c++)
#pragma unroll
                for (int d = 0; d < 4; d++) o[a][b][c][d] = 0.0f;
    float il[4];
#pragma unroll
    for (int i = 0; i < 4; i++) il[i] = inv_sh[r0 + i];

    for (int kt = 0; kt <= qt; kt++) {
        float4 pv[4];
#pragma unroll
        for (int i = 0; i < 4; i++) {
            float4 v = *(const float4*)&sh[(size_t)(qbase + r0 + i) * S_LEN + kt * 64 + c0];
            v.x *= il[i]; v.y *= il[i]; v.z *= il[i]; v.w *= il[i];
            pv[i] = v;
        }
        __syncthreads();        // previous iteration's sP readers done
#pragma unroll
        for (int i = 0; i < 4; i++)
            *(float4*)&sP[(r0 + i) * 68 + c0] = pv[i];
        __syncthreads();

        if (tid < 64) {
            float cs = 0.0f;
#pragma unroll 8
            for (int q = 0; q < 64; q++) cs += sP[q * 68 + tid];
            g_colpart[((size_t)h * NQT + qt) * S_LEN + kt * 64 + tid] = cs;
        }

#pragma unroll
        for (int hlf = 0; hlf < 2; hlf++) {
            __syncthreads();    // previous Vs readers done
            {
                const int key = tid >> 4;
                const int dd = (tid & 15) * 4;
#pragma unroll
                for (int i = 0; i < 4; i++) {
                    float4 v = *(const float4*)&g_v[(size_t)(kt * 64 + key + 16 * i) * KV_DM +
                                                    kvh * HDIM + hlf * 64 + dd];
                    *(float4*)&Vs[(key + 16 * i) * 72 + dd] = v;
                }
            }
            __syncthreads();
#pragma unroll
            for (int ks = 0; ks < 8; ks++) {
                const int kk = ks * 8;
                uint32_t af[2][4], bf[2][2];
#pragma unroll
                for (int mi = 0; mi < 2; mi++) {
                    int m0 = wm0 + 16 * mi + (lane >> 2);
                    af[mi][0] = __float_as_uint(sP[m0 * 68 + kk + (lane & 3)]);
                    af[mi][1] = __float_as_uint(sP[(m0 + 8) * 68 + kk + (lane & 3)]);
                    af[mi][2] = __float_as_uint(sP[m0 * 68 + kk + 4 + (lane & 3)]);
                    af[mi][3] = __float_as_uint(sP[(m0 + 8) * 68 + kk + 4 + (lane & 3)]);
                }
#pragma unroll
                for (int nj = 0; nj < 2; nj++) {
                    int n0 = wn0 + 8 * nj + (lane >> 2);
                    bf[nj][0] = __float_as_uint(Vs[(kk + (lane & 3)) * 72 + n0]);
                    bf[nj][1] = __float_as_uint(Vs[(kk + 4 + (lane & 3)) * 72 + n0]);
                }
#pragma unroll
                for (int mi = 0; mi < 2; mi++)
#pragma unroll
                    for (int nj = 0; nj < 2; nj++)
                        mma_tf32(o[hlf][mi][nj], af[mi], bf[nj]);
            }
        }
    }

#pragma unroll
    for (int hlf = 0; hlf < 2; hlf++)
#pragma unroll
        for (int mi = 0; mi < 2; mi++)
#pragma unroll
            for (int nj = 0; nj < 2; nj++) {
                int row = qbase + wm0 + 16 * mi + (lane >> 2);
                int col = h * HDIM + hlf * 64 + wn0 + 8 * nj + 2 * (lane & 3);
                *(float2*)&g_ctx[(size_t)row * DMODEL + col] =
                    make_float2(o[hlf][mi][nj][0], o[hlf][mi][nj][1]);
                *(float2*)&g_ctx[(size_t)(row + 8) * DMODEL + col] =
                    make_float2(o[hlf][mi][nj][2], o[hlf][mi][nj][3]);
            }
}

// ---------------------------------------------------------------------------
// Heavy-hitter mask (deterministic top-k, lowest index on ties).
// ---------------------------------------------------------------------------
__global__ __launch_bounds__(256) void topk_kernel(float* __restrict__ mask_out) {
    const int h = blockIdx.x;
    const int tid = threadIdx.x;
    __shared__ float vals[SEL];
    __shared__ float bv[256];
    __shared__ int   bi[256];

    for (int i = tid; i < SEL; i += 256) {
        float s = 0.0f;
        for (int qt = 0; qt < NQT; qt++)
            s += g_colpart[((size_t)h * NQT + qt) * S_LEN + i];
        vals[i] = s;
    }
    float* mrow = mask_out + (size_t)h * MASKW;
    for (int i = tid; i < MASKW; i += 256)
        mrow[i] = (i >= (MASKW - RECENT)) ? 1.0f : 0.0f;
    __syncthreads();

    for (int it = 0; it < HEAVY; it++) {
        float best = -1.0f;
        int besti = SEL;
        for (int i = tid; i < SEL; i += 256) {
            float v = vals[i];
            if (v > best) { best = v; besti = i; }
        }
        bv[tid] = best; bi[tid] = besti;
        __syncthreads();
        for (int s = 128; s > 0; s >>= 1) {
            if (tid < s) {
                float ov = bv[tid + s]; int oi = bi[tid + s];
                if (ov > bv[tid] || (ov == bv[tid] && oi < bi[tid])) { bv[tid] = ov; bi[tid] = oi; }
            }
            __syncthreads();
        }
        if (tid == 0) { mrow[bi[0]] = 1.0f; vals[bi[0]] = -1.0f; }
        __syncthreads();
    }
}

// ---------------------------------------------------------------------------
extern "C" void kernel_launch(void* const* d_in, const int* in_sizes, int n_in,
                              void* d_out, int out_size) {
    (void)in_sizes; (void)n_in; (void)out_size;
    const float* hidden = (const float*)d_in[0];
    const float* q_w = (const float*)d_in[1];
    const float* q_b = (const float*)d_in[2];
    const float* k_w = (const float*)d_in[3];
    const float* k_b = (const float*)d_in[4];
    const float* v_w = (const float*)d_in[5];
    const float* v_b = (const float*)d_in[6];
    const float* o_w = (const float*)d_in[7];
    float* out = (float*)d_out;

    float *gq, *gk, *gv, *gctx, *gcp;
    cudaGetSymbolAddress((void**)&gq,   g_q);
    cudaGetSymbolAddress((void**)&gk,   g_k);
    cudaGetSymbolAddress((void**)&gv,   g_v);
    cudaGetSymbolAddress((void**)&gctx, g_ctx);
    cudaGetSymbolAddress((void**)&gcp,  g_colpart);

    const int ncp = NH * NQT * S_LEN;
    zero_kernel<<<(ncp + 255) / 256, 256>>>(gcp, ncp);

    gemm_tf32<128, 64, 32><<<dim3(DMODEL / 128, S_LEN / 128), 256>>>(
        hidden, q_w, q_b, gq, S_LEN, DMODEL, DMODEL);
    gemm_tf32<64, 32, 32><<<dim3(KV_DM / 64, S_LEN / 128), 256>>>(
        hidden, k_w, k_b, gk, S_LEN, KV_DM, DMODEL);
    gemm_tf32<64, 32, 32><<<dim3(KV_DM / 64, S_LEN / 128), 256>>>(
        hidden, v_w, v_b, gv, S_LEN, KV_DM, DMODEL);

    scores_tf32<<<dim3(S_LEN / 128, S_LEN / 128, NH), 256>>>();

    attn_kernel<<<dim3(NQT, NH), 256>>>();

    topk_kernel<<<NH, 256>>>(out + (size_t)S_LEN * DMODEL);

    gemm_tf32<128, 64, 32><<<dim3(DMODEL / 128, S_LEN / 128), 256>>>(
        gctx, o_w, nullptr, out, S_LEN, DMODEL, DMODEL);
}